// round 5
// baseline (speedup 1.0000x reference)
#include <cuda_runtime.h>

#define NN 50000
#define EE 600000
#define HH 128
#define NG 64

// ---------------- static scratch (allocation-free rule) ----------------
__device__ float g_agg[NN * HH];        // mean-aggregated features
__device__ float g_hA[NN * HH];         // ping
__device__ float g_hB[NN * HH];         // pong
__device__ int   g_deg[3][NN];
__device__ int   g_off[3][NN + 1];
__device__ int   g_cur[3][NN];
__device__ int   g_csr[3][EE];
__device__ float g_pool[NG * HH];

// ---------------- CSR build ----------------
__global__ void k_zero_deg() {
    int i = blockIdx.x * blockDim.x + threadIdx.x;
    if (i < 3 * NN) ((int*)g_deg)[i] = 0;
}

// edge arrays are [2, E] row-major: src = e[0..E), dst = e[E..2E)
__global__ void k_hist(const int* __restrict__ e0, const int* __restrict__ e1,
                       const int* __restrict__ e2) {
    int i = blockIdx.x * blockDim.x + threadIdx.x;
    if (i >= EE) return;
    atomicAdd(&g_deg[0][e0[EE + i]], 1);
    atomicAdd(&g_deg[1][e1[EE + i]], 1);
    atomicAdd(&g_deg[2][e2[EE + i]], 1);
}

// one block per edge list; 1024-thread chunked exclusive scan
__global__ void k_scan() {
    int lst = blockIdx.x;
    __shared__ int wsum[32];
    __shared__ int carry;
    int t = threadIdx.x;
    int wid = t >> 5, lane = t & 31;
    if (t == 0) carry = 0;
    __syncthreads();
    for (int base = 0; base < NN; base += 1024) {
        int i = base + t;
        int v = (i < NN) ? g_deg[lst][i] : 0;
        int x = v;
#pragma unroll
        for (int o = 1; o < 32; o <<= 1) {
            int y = __shfl_up_sync(0xffffffffu, x, o);
            if (lane >= o) x += y;
        }
        __syncthreads();
        if (lane == 31) wsum[wid] = x;
        __syncthreads();
        if (t < 32) {
            int xx = wsum[t];
#pragma unroll
            for (int o = 1; o < 32; o <<= 1) {
                int y = __shfl_up_sync(0xffffffffu, xx, o);
                if (t >= o) xx += y;
            }
            wsum[t] = xx;
        }
        __syncthreads();
        int wb = wid ? wsum[wid - 1] : 0;
        int excl = carry + wb + x - v;
        if (i < NN) { g_off[lst][i] = excl; g_cur[lst][i] = excl; }
        __syncthreads();
        if (t == 0) carry += wsum[31];
        __syncthreads();
    }
    if (t == 0) g_off[lst][NN] = carry;
}

__global__ void k_fill(const int* __restrict__ e, int lst) {
    int i = blockIdx.x * blockDim.x + threadIdx.x;
    if (i >= EE) return;
    int d = e[EE + i];
    int p = atomicAdd(&g_cur[lst][d], 1);
    g_csr[lst][p] = e[i];
}

// ---------------- mean aggregation: warp per node, no float atomics ----------------
__global__ void k_agg(const float* __restrict__ h, int lst) {
    int node = (blockIdx.x * blockDim.x + threadIdx.x) >> 5;
    if (node >= NN) return;
    int lane = threadIdx.x & 31;
    int s = g_off[lst][node], e = g_off[lst][node + 1];
    const int* csr = g_csr[lst];
    float4 acc = make_float4(0.f, 0.f, 0.f, 0.f);
    for (int i = s; i < e; i++) {
        int src = csr[i];
        float4 v = __ldg((const float4*)(h + (size_t)src * HH + lane * 4));
        acc.x += v.x; acc.y += v.y; acc.z += v.z; acc.w += v.w;
    }
    float inv = 1.0f / fmaxf((float)(e - s), 1.0f);
    acc.x *= inv; acc.y *= inv; acc.z *= inv; acc.w *= inv;
    *(float4*)(g_agg + (size_t)node * HH + lane * 4) = acc;
}

// ---------------- SAGE GEMM: out = agg@Wl + bl + x@Wr (+ optional L2 norm) ----------
// block tile 128 rows x 128 cols, 256 threads, 8x8 register tile per thread
__global__ __launch_bounds__(256) void k_sage(
    const float* __restrict__ Xin,
    const float* __restrict__ Wl, const float* __restrict__ bl,
    const float* __restrict__ Wr, float* __restrict__ out, int donorm) {
    __shared__ float As[16][128];
    __shared__ float Bs[16][128];
    const int tid = threadIdx.x;
    const int tm = tid >> 4;   // 0..15
    const int tn = tid & 15;   // 0..15
    const int rowBase = blockIdx.x * 128;

    float acc[8][8];
#pragma unroll
    for (int i = 0; i < 8; i++)
#pragma unroll
        for (int j = 0; j < 8; j++) acc[i][j] = 0.f;

#pragma unroll 1
    for (int phase = 0; phase < 2; phase++) {
        const float* A = phase ? Xin : g_agg;
        const float* W = phase ? Wr : Wl;
#pragma unroll 1
        for (int k0 = 0; k0 < 128; k0 += 16) {
            // A tile: 128 rows x 16 k, transposed into As[k][m]
#pragma unroll
            for (int i = 0; i < 2; i++) {
                int f = tid + i * 256;
                int r = f >> 2;
                int kq = f & 3;
                int grow = rowBase + r;
                float4 v = make_float4(0.f, 0.f, 0.f, 0.f);
                if (grow < NN) v = *(const float4*)(A + (size_t)grow * 128 + k0 + kq * 4);
                As[kq * 4 + 0][r] = v.x;
                As[kq * 4 + 1][r] = v.y;
                As[kq * 4 + 2][r] = v.z;
                As[kq * 4 + 3][r] = v.w;
            }
            // B tile: 16 k x 128 cols, direct
#pragma unroll
            for (int i = 0; i < 2; i++) {
                int f = tid + i * 256;
                int kk = f >> 5;
                int c4 = f & 31;
                *(float4*)&Bs[kk][c4 * 4] =
                    *(const float4*)(W + (size_t)(k0 + kk) * 128 + c4 * 4);
            }
            __syncthreads();
#pragma unroll
            for (int k = 0; k < 16; k++) {
                float a[8], b[8];
                *(float4*)&a[0] = *(const float4*)&As[k][tm * 8];
                *(float4*)&a[4] = *(const float4*)&As[k][tm * 8 + 4];
                *(float4*)&b[0] = *(const float4*)&Bs[k][tn * 8];
                *(float4*)&b[4] = *(const float4*)&Bs[k][tn * 8 + 4];
#pragma unroll
                for (int i = 0; i < 8; i++)
#pragma unroll
                    for (int j = 0; j < 8; j++) acc[i][j] = fmaf(a[i], b[j], acc[i][j]);
            }
            __syncthreads();
        }
    }

    // epilogue: bias, optional row L2 normalize, store
    float bb[8];
#pragma unroll
    for (int j = 0; j < 8; j++) bb[j] = bl[tn * 8 + j];
#pragma unroll
    for (int i = 0; i < 8; i++)
#pragma unroll
        for (int j = 0; j < 8; j++) acc[i][j] += bb[j];

    if (donorm) {
        // the 16 threads sharing tm hold all 128 cols of each of this thread's 8 rows;
        // they are 16 consecutive lanes (tid = tm*16+tn), so xor-shuffles over bits 0..3
        // stay inside the group.
#pragma unroll
        for (int i = 0; i < 8; i++) {
            float s = 0.f;
#pragma unroll
            for (int j = 0; j < 8; j++) s += acc[i][j] * acc[i][j];
            s += __shfl_xor_sync(0xffffffffu, s, 1);
            s += __shfl_xor_sync(0xffffffffu, s, 2);
            s += __shfl_xor_sync(0xffffffffu, s, 4);
            s += __shfl_xor_sync(0xffffffffu, s, 8);
            float inv = 1.0f / fmaxf(sqrtf(s), 1e-12f);
#pragma unroll
            for (int j = 0; j < 8; j++) acc[i][j] *= inv;
        }
    }
#pragma unroll
    for (int i = 0; i < 8; i++) {
        int row = rowBase + tm * 8 + i;
        if (row < NN) {
            *(float4*)(out + (size_t)row * 128 + tn * 8) =
                make_float4(acc[i][0], acc[i][1], acc[i][2], acc[i][3]);
            *(float4*)(out + (size_t)row * 128 + tn * 8 + 4) =
                make_float4(acc[i][4], acc[i][5], acc[i][6], acc[i][7]);
        }
    }
}

// ---------------- global add pool (batch is sorted -> binary search) --------------
__global__ void k_pool(const float* __restrict__ h, const int* __restrict__ batch) {
    int gi = blockIdx.x;
    int lo, hi;
    {
        int a = 0, b = NN;
        while (a < b) { int m = (a + b) >> 1; if (batch[m] < gi) a = m + 1; else b = m; }
        lo = a;
    }
    {
        int a = lo, b = NN;
        while (a < b) { int m = (a + b) >> 1; if (batch[m] < gi + 1) a = m + 1; else b = m; }
        hi = a;
    }
    int t = threadIdx.x;
    float s = 0.f;
    for (int n = lo; n < hi; n++) s += h[(size_t)n * 128 + t];
    g_pool[gi * 128 + t] = s;
}

// ---------------- MLP head: relu(g@W0+b0) -> relu(@W1+b1) -> @Wh+bh --------------
__global__ void k_mlp(const float* __restrict__ W0, const float* __restrict__ b0,
                      const float* __restrict__ W1, const float* __restrict__ b1,
                      const float* __restrict__ Wh, const float* __restrict__ bh,
                      float* __restrict__ out) {
    int gi = blockIdx.x;
    int t = threadIdx.x;  // 128
    __shared__ float r0[128], r1[128];
    __shared__ float ws[4];
    r0[t] = g_pool[gi * 128 + t];
    __syncthreads();
    float s = b0[t];
#pragma unroll 8
    for (int k = 0; k < 128; k++) s = fmaf(r0[k], W0[k * 128 + t], s);
    r1[t] = fmaxf(s, 0.f);
    __syncthreads();
    float s2 = b1[t];
#pragma unroll 8
    for (int k = 0; k < 128; k++) s2 = fmaf(r1[k], W1[k * 128 + t], s2);
    float h = fmaxf(s2, 0.f);
    float p = h * Wh[t];
#pragma unroll
    for (int o = 16; o; o >>= 1) p += __shfl_xor_sync(0xffffffffu, p, o);
    if ((t & 31) == 0) ws[t >> 5] = p;
    __syncthreads();
    if (t == 0) out[gi] = ws[0] + ws[1] + ws[2] + ws[3] + bh[0];
}

// ---------------- orchestration ----------------
extern "C" void kernel_launch(void* const* d_in, const int* in_sizes, int n_in,
                              void* d_out, int out_size) {
    const float* x   = (const float*)d_in[0];
    const int*  eic  = (const int*)d_in[1];
    const int*  eid  = (const int*)d_in[2];
    const int*  eit  = (const int*)d_in[3];
    const int*  batch = (const int*)d_in[4];
    const float* cWl[5], *cbl[5], *cWr[5];
    for (int c = 0; c < 5; c++) {
        cWl[c] = (const float*)d_in[5 + 3 * c];
        cbl[c] = (const float*)d_in[6 + 3 * c];
        cWr[c] = (const float*)d_in[7 + 3 * c];
    }
    const float* l0W = (const float*)d_in[20];
    const float* l0b = (const float*)d_in[21];
    const float* l1W = (const float*)d_in[22];
    const float* l1b = (const float*)d_in[23];
    const float* hW  = (const float*)d_in[24];
    const float* hb  = (const float*)d_in[25];
    float* out = (float*)d_out;

    float *hA = nullptr, *hB = nullptr;
    cudaGetSymbolAddress((void**)&hA, g_hA);
    cudaGetSymbolAddress((void**)&hB, g_hB);

    // CSR build for the 3 edge lists (list 0=eic, 1=eid, 2=eit)
    k_zero_deg<<<(3 * NN + 255) / 256, 256>>>();
    k_hist<<<(EE + 255) / 256, 256>>>(eic, eid, eit);
    k_scan<<<3, 1024>>>();
    k_fill<<<(EE + 255) / 256, 256>>>(eic, 0);
    k_fill<<<(EE + 255) / 256, 256>>>(eid, 1);
    k_fill<<<(EE + 255) / 256, 256>>>(eit, 2);

    // layer schedule: edge list id, conv weight id, normalize flag
    const int lst[7]  = {1, 0, 0, 2, 1, 0, 0};
    const int conv[7] = {0, 1, 1, 2, 3, 4, 4};
    const int nrm[7]  = {1, 1, 1, 0, 1, 1, 1};

    const float* hin = x;
    float* hout = hA;
    for (int L = 0; L < 7; L++) {
        k_agg<<<(NN * 32 + 255) / 256, 256>>>(hin, lst[L]);
        k_sage<<<(NN + 127) / 128, 256>>>(hin, cWl[conv[L]], cbl[conv[L]],
                                          cWr[conv[L]], hout, nrm[L]);
        hin = hout;
        hout = (hout == hA) ? hB : hA;
    }

    k_pool<<<NG, 128>>>(hin, batch);
    k_mlp<<<NG, 128>>>(l0W, l0b, l1W, l1b, hW, hb, out);
}

// round 7
// speedup vs baseline: 1.3977x; 1.3977x over previous
#include <cuda_runtime.h>
#include <cuda_bf16.h>

#define NN 50000
#define EE 600000
#define HH 128
#define NG 64

// ---------------- static scratch (allocation-free rule) ----------------
__device__ float g_agg[NN * HH];
__device__ float g_hA[NN * HH];
__device__ float g_hB[NN * HH];
__device__ int   g_deg[3][NN];
__device__ int   g_off[3][NN + 1];
__device__ int   g_cur[3][NN];
__device__ int   g_csr[3][EE];
__device__ float g_pool[NG * HH];
// bf16 weight images, transposed to [n][k] row-major, unpadded 32KB each:
// [conv][mat(Wl=0,Wr=1)][hi=0/lo=1]
__device__ __align__(16) __nv_bfloat16 g_wblob[5][2][2][HH * HH];

// ---------------- CSR build ----------------
__global__ void k_zero_deg() {
    int i = blockIdx.x * blockDim.x + threadIdx.x;
    if (i < 3 * NN) ((int*)g_deg)[i] = 0;
}
__global__ void k_hist(const int* __restrict__ e0, const int* __restrict__ e1,
                       const int* __restrict__ e2) {
    int i = blockIdx.x * blockDim.x + threadIdx.x;
    if (i >= EE) return;
    atomicAdd(&g_deg[0][e0[EE + i]], 1);
    atomicAdd(&g_deg[1][e1[EE + i]], 1);
    atomicAdd(&g_deg[2][e2[EE + i]], 1);
}
__global__ void k_scan() {
    int lst = blockIdx.x;
    __shared__ int wsum[32];
    __shared__ int carry;
    int t = threadIdx.x, wid = t >> 5, lane = t & 31;
    if (t == 0) carry = 0;
    __syncthreads();
    for (int base = 0; base < NN; base += 1024) {
        int i = base + t;
        int v = (i < NN) ? g_deg[lst][i] : 0;
        int x = v;
#pragma unroll
        for (int o = 1; o < 32; o <<= 1) {
            int y = __shfl_up_sync(0xffffffffu, x, o);
            if (lane >= o) x += y;
        }
        __syncthreads();
        if (lane == 31) wsum[wid] = x;
        __syncthreads();
        if (t < 32) {
            int xx = wsum[t];
#pragma unroll
            for (int o = 1; o < 32; o <<= 1) {
                int y = __shfl_up_sync(0xffffffffu, xx, o);
                if (t >= o) xx += y;
            }
            wsum[t] = xx;
        }
        __syncthreads();
        int wb = wid ? wsum[wid - 1] : 0;
        int excl = carry + wb + x - v;
        if (i < NN) { g_off[lst][i] = excl; g_cur[lst][i] = excl; }
        __syncthreads();
        if (t == 0) carry += wsum[31];
        __syncthreads();
    }
    if (t == 0) g_off[lst][NN] = carry;
}
__global__ void k_fill(const int* __restrict__ e, int lst) {
    int i = blockIdx.x * blockDim.x + threadIdx.x;
    if (i >= EE) return;
    int d = e[EE + i];
    int p = atomicAdd(&g_cur[lst][d], 1);
    g_csr[lst][p] = e[i];
}

// ---------------- mean aggregation: warp per node, no float atomics ----------------
__global__ void k_agg(const float* __restrict__ h, int lst) {
    int node = (blockIdx.x * blockDim.x + threadIdx.x) >> 5;
    if (node >= NN) return;
    int lane = threadIdx.x & 31;
    int s = g_off[lst][node], e = g_off[lst][node + 1];
    const int* csr = g_csr[lst];
    float4 acc = make_float4(0.f, 0.f, 0.f, 0.f);
    for (int i = s; i < e; i++) {
        int src = csr[i];
        float4 v = __ldg((const float4*)(h + (size_t)src * HH + lane * 4));
        acc.x += v.x; acc.y += v.y; acc.z += v.z; acc.w += v.w;
    }
    float inv = 1.0f / fmaxf((float)(e - s), 1.0f);
    acc.x *= inv; acc.y *= inv; acc.z *= inv; acc.w *= inv;
    *(float4*)(g_agg + (size_t)node * HH + lane * 4) = acc;
}

// ---------------- weight prep: fp32 W[k][n] -> bf16 hi/lo images B[n][k] ----------
__global__ void k_wprep(const float* __restrict__ W, int c, int mat) {
    int idx = blockIdx.x * blockDim.x + threadIdx.x;  // 0..16383
    int n = idx >> 7, k = idx & 127;
    float v = W[k * 128 + n];
    __nv_bfloat16 hi = __float2bfloat16(v);
    __nv_bfloat16 lo = __float2bfloat16(v - __bfloat162float(hi));
    g_wblob[c][mat][0][n * 128 + k] = hi;
    g_wblob[c][mat][1][n * 128 + k] = lo;
}

// ---------------- mma.sync bf16 SAGE GEMM ----------------
// out[128 x 128] = agg@Wl + x@Wr + bl (+ optional row L2 norm)
// 3-term bf16 split per phase: hi*hi + lo*hi + hi*lo, fp32 accum.
//
// SMEM: 4 bf16 tiles [128 rows][128 cols], row stride 272B (128 cols + 16B pad)
//   -> word stride 68, uint4 stride 17. Conflict-free fragment LDS.
#define PADW 68                         // 32-bit words per padded row
#define TILE_B (128 * PADW * 4)         // 34816 bytes per tile
#define OFF_AHI 0
#define OFF_ALO TILE_B
#define OFF_WHI (2 * TILE_B)
#define OFF_WLO (3 * TILE_B)
#define SM_TOTAL (4 * TILE_B)           // 139264 bytes
#define CSTRIDE 132                     // fp32 epilogue tile stride (16B aligned)

__device__ __forceinline__ void mma16816(float* c, const unsigned* a, const unsigned* b) {
    asm volatile(
        "mma.sync.aligned.m16n8k16.row.col.f32.bf16.bf16.f32 "
        "{%0,%1,%2,%3}, {%4,%5,%6,%7}, {%8,%9}, {%0,%1,%2,%3};"
        : "+f"(c[0]), "+f"(c[1]), "+f"(c[2]), "+f"(c[3])
        : "r"(a[0]), "r"(a[1]), "r"(a[2]), "r"(a[3]), "r"(b[0]), "r"(b[1]));
}

__global__ __launch_bounds__(256, 1) void k_sage_mma(
    const float* __restrict__ Xin, const float* __restrict__ bl,
    int conv, float* __restrict__ out, int donorm) {
    extern __shared__ char smem[];
    const int tid = threadIdx.x;
    const int wid = tid >> 5, lane = tid & 31;
    const int g = lane >> 2, t = lane & 3;
    const int m0 = (wid >> 1) * 32;       // warp m-origin (4 rows of warps)
    const int n0 = (wid & 1) * 64;        // warp n-origin (2 cols of warps)
    const int rowBase = blockIdx.x * 128;

    float acc[2][8][4];
#pragma unroll
    for (int mi = 0; mi < 2; mi++)
#pragma unroll
        for (int ni = 0; ni < 8; ni++)
#pragma unroll
            for (int r = 0; r < 4; r++) acc[mi][ni][r] = 0.f;

#pragma unroll 1
    for (int phase = 0; phase < 2; phase++) {
        const float* A = phase ? Xin : g_agg;
        // --- A tile: fp32 load -> bf16 hi/lo split into padded SMEM ---
#pragma unroll 4
        for (int i = 0; i < 16; i++) {
            int v = i * 256 + tid;        // 4096 float4 per 128x128 tile
            int r = v >> 5, c4 = v & 31;  // 32 float4 per row
            int grow = rowBase + r;
            float4 f = make_float4(0.f, 0.f, 0.f, 0.f);
            if (grow < NN) f = __ldg((const float4*)(A + (size_t)grow * 128 + c4 * 4));
            __nv_bfloat162 h0, h1, l0, l1;
            h0.x = __float2bfloat16(f.x); h0.y = __float2bfloat16(f.y);
            h1.x = __float2bfloat16(f.z); h1.y = __float2bfloat16(f.w);
            l0.x = __float2bfloat16(f.x - __bfloat162float(h0.x));
            l0.y = __float2bfloat16(f.y - __bfloat162float(h0.y));
            l1.x = __float2bfloat16(f.z - __bfloat162float(h1.x));
            l1.y = __float2bfloat16(f.w - __bfloat162float(h1.y));
            unsigned off = (unsigned)r * 272 + c4 * 8;
            *(__nv_bfloat162*)(smem + OFF_AHI + off)     = h0;
            *(__nv_bfloat162*)(smem + OFF_AHI + off + 4) = h1;
            *(__nv_bfloat162*)(smem + OFF_ALO + off)     = l0;
            *(__nv_bfloat162*)(smem + OFF_ALO + off + 4) = l1;
        }
        // --- W tiles: copy 32KB hi/lo blobs into padded SMEM ---
        {
            const uint4* bh = (const uint4*)g_wblob[conv][phase][0];
            const uint4* bo = (const uint4*)g_wblob[conv][phase][1];
            uint4* wh = (uint4*)(smem + OFF_WHI);
            uint4* wl = (uint4*)(smem + OFF_WLO);
#pragma unroll 4
            for (int i = 0; i < 8; i++) {
                int v = i * 256 + tid;    // 2048 uint4 per blob
                int r = v >> 4, c = v & 15;
                wh[r * 17 + c] = __ldg(bh + v);
                wl[r * 17 + c] = __ldg(bo + v);
            }
        }
        __syncthreads();

        // --- compute: 3 split terms x 8 k-steps ---
        const unsigned* su = (const unsigned*)smem;
#pragma unroll 1
        for (int term = 0; term < 3; term++) {
            const unsigned* Au = su + ((term == 1) ? OFF_ALO : OFF_AHI) / 4;
            const unsigned* Wu = su + ((term == 2) ? OFF_WLO : OFF_WHI) / 4;
#pragma unroll
            for (int k0 = 0; k0 < 8; k0++) {
                const int kw = k0 * 8 + t;   // word column within row
                unsigned a[2][4];
#pragma unroll
                for (int mi = 0; mi < 2; mi++) {
                    int rw = (m0 + mi * 16 + g) * PADW + kw;
                    a[mi][0] = Au[rw];
                    a[mi][1] = Au[rw + 8 * PADW];
                    a[mi][2] = Au[rw + 4];
                    a[mi][3] = Au[rw + 8 * PADW + 4];
                }
                unsigned b[8][2];
#pragma unroll
                for (int ni = 0; ni < 8; ni++) {
                    int rw = (n0 + ni * 8 + g) * PADW + kw;
                    b[ni][0] = Wu[rw];
                    b[ni][1] = Wu[rw + 4];
                }
#pragma unroll
                for (int mi = 0; mi < 2; mi++)
#pragma unroll
                    for (int ni = 0; ni < 8; ni++)
                        mma16816(acc[mi][ni], a[mi], b[ni]);
            }
        }
        __syncthreads();
    }

    // --- epilogue: acc -> SMEM fp32 tile, then one thread per row ---
    float* smC = (float*)smem;
#pragma unroll
    for (int mi = 0; mi < 2; mi++)
#pragma unroll
        for (int ni = 0; ni < 8; ni++) {
            int row = m0 + mi * 16 + g;
            int col = n0 + ni * 8 + t * 2;
            smC[row * CSTRIDE + col]               = acc[mi][ni][0];
            smC[row * CSTRIDE + col + 1]           = acc[mi][ni][1];
            smC[(row + 8) * CSTRIDE + col]         = acc[mi][ni][2];
            smC[(row + 8) * CSTRIDE + col + 1]     = acc[mi][ni][3];
        }
    __syncthreads();

    if (tid < 128) {
        int row = rowBase + tid;
        float d[128];
#pragma unroll
        for (int c = 0; c < 128; c += 4) {
            float4 v = *(const float4*)(smC + tid * CSTRIDE + c);
            float4 bb = __ldg((const float4*)(bl + c));
            d[c]     = v.x + bb.x;
            d[c + 1] = v.y + bb.y;
            d[c + 2] = v.z + bb.z;
            d[c + 3] = v.w + bb.w;
        }
        if (donorm) {
            float s = 0.f;
#pragma unroll
            for (int c = 0; c < 128; c++) s = fmaf(d[c], d[c], s);
            float inv = 1.0f / fmaxf(sqrtf(s), 1e-12f);
#pragma unroll
            for (int c = 0; c < 128; c++) d[c] *= inv;
        }
        if (row < NN) {
            float* op = out + (size_t)row * 128;
#pragma unroll
            for (int c = 0; c < 128; c += 4)
                *(float4*)(op + c) = make_float4(d[c], d[c + 1], d[c + 2], d[c + 3]);
        }
    }
}

// ---------------- global add pool (batch sorted -> binary search) --------------
__global__ void k_pool(const float* __restrict__ h, const int* __restrict__ batch) {
    int gi = blockIdx.x;
    int lo, hi;
    { int a = 0, b = NN; while (a < b) { int m = (a + b) >> 1; if (batch[m] < gi) a = m + 1; else b = m; } lo = a; }
    { int a = lo, b = NN; while (a < b) { int m = (a + b) >> 1; if (batch[m] < gi + 1) a = m + 1; else b = m; } hi = a; }
    int t = threadIdx.x;
    float s = 0.f;
    for (int n = lo; n < hi; n++) s += h[(size_t)n * 128 + t];
    g_pool[gi * 128 + t] = s;
}

// ---------------- MLP head ----------------
__global__ void k_mlp(const float* __restrict__ W0, const float* __restrict__ b0,
                      const float* __restrict__ W1, const float* __restrict__ b1,
                      const float* __restrict__ Wh, const float* __restrict__ bh,
                      float* __restrict__ out) {
    int gi = blockIdx.x, t = threadIdx.x;
    __shared__ float r0[128], r1[128];
    __shared__ float ws[4];
    r0[t] = g_pool[gi * 128 + t];
    __syncthreads();
    float s = b0[t];
#pragma unroll 8
    for (int k = 0; k < 128; k++) s = fmaf(r0[k], W0[k * 128 + t], s);
    r1[t] = fmaxf(s, 0.f);
    __syncthreads();
    float s2 = b1[t];
#pragma unroll 8
    for (int k = 0; k < 128; k++) s2 = fmaf(r1[k], W1[k * 128 + t], s2);
    float h = fmaxf(s2, 0.f);
    float p = h * Wh[t];
#pragma unroll
    for (int o = 16; o; o >>= 1) p += __shfl_xor_sync(0xffffffffu, p, o);
    if ((t & 31) == 0) ws[t >> 5] = p;
    __syncthreads();
    if (t == 0) out[gi] = ws[0] + ws[1] + ws[2] + ws[3] + bh[0];
}

// ---------------- orchestration ----------------
extern "C" void kernel_launch(void* const* d_in, const int* in_sizes, int n_in,
                              void* d_out, int out_size) {
    const float* x    = (const float*)d_in[0];
    const int*  eic   = (const int*)d_in[1];
    const int*  eid   = (const int*)d_in[2];
    const int*  eit   = (const int*)d_in[3];
    const int*  batch = (const int*)d_in[4];
    const float* cWl[5], *cbl[5], *cWr[5];
    for (int c = 0; c < 5; c++) {
        cWl[c] = (const float*)d_in[5 + 3 * c];
        cbl[c] = (const float*)d_in[6 + 3 * c];
        cWr[c] = (const float*)d_in[7 + 3 * c];
    }
    const float* l0W = (const float*)d_in[20];
    const float* l0b = (const float*)d_in[21];
    const float* l1W = (const float*)d_in[22];
    const float* l1b = (const float*)d_in[23];
    const float* hW  = (const float*)d_in[24];
    const float* hb  = (const float*)d_in[25];
    float* out = (float*)d_out;

    float *hA = nullptr, *hB = nullptr;
    cudaGetSymbolAddress((void**)&hA, g_hA);
    cudaGetSymbolAddress((void**)&hB, g_hB);

    cudaFuncSetAttribute(k_sage_mma, cudaFuncAttributeMaxDynamicSharedMemorySize, SM_TOTAL);

    // CSR build (3 edge lists)
    k_zero_deg<<<(3 * NN + 255) / 256, 256>>>();
    k_hist<<<(EE + 255) / 256, 256>>>(eic, eid, eit);
    k_scan<<<3, 1024>>>();
    k_fill<<<(EE + 255) / 256, 256>>>(eic, 0);
    k_fill<<<(EE + 255) / 256, 256>>>(eid, 1);
    k_fill<<<(EE + 255) / 256, 256>>>(eit, 2);

    // weight blobs (bf16 hi/lo, transposed to [n][k])
    for (int c = 0; c < 5; c++) {
        k_wprep<<<64, 256>>>(cWl[c], c, 0);
        k_wprep<<<64, 256>>>(cWr[c], c, 1);
    }

    const int lst[7]  = {1, 0, 0, 2, 1, 0, 0};
    const int conv[7] = {0, 1, 1, 2, 3, 4, 4};
    const int nrm[7]  = {1, 1, 1, 0, 1, 1, 1};

    const float* hin = x;
    float* hout = hA;
    for (int L = 0; L < 7; L++) {
        k_agg<<<(NN * 32 + 255) / 256, 256>>>(hin, lst[L]);
        k_sage_mma<<<(NN + 127) / 128, 256, SM_TOTAL>>>(hin, cbl[conv[L]], conv[L],
                                                        hout, nrm[L]);
        hin = hout;
        hout = (hout == hA) ? hB : hA;
    }

    k_pool<<<NG, 128>>>(hin, batch);
    k_mlp<<<NG, 128>>>(l0W, l0b, l1W, l1b, hW, hb, out);
}